// round 6
// baseline (speedup 1.0000x reference)
#include <cuda_runtime.h>
#include <cuda_bf16.h>
#include <cstdint>
#include <math.h>

#define B 4
#define C 64
#define N 4096

// ---------------------------------------------------------------------------
// Scratch (device globals, allocation-free rule)
// ---------------------------------------------------------------------------
__device__ __align__(16) __nv_bfloat16 g_Qb[B * N * 8];   // [b][n][8], scaled 0.125*log2e
__device__ __align__(16) __nv_bfloat16 g_Kb[B * N * 8];   // [b][m][8]
__device__ __align__(16) __nv_bfloat16 g_Vt[B * C * N];   // [b][ch][m] transposed
__device__ float g_gate[B * C];
__device__ float g_part[B * 64 * C];                       // per-CTA channel sums

// ---------------------------------------------------------------------------
// Helpers
// ---------------------------------------------------------------------------
__device__ __forceinline__ uint32_t smem_u32(const void* p) {
    uint32_t a;
    asm("{ .reg .u64 t; cvta.to.shared.u64 t, %1; cvt.u32.u64 %0, t; }" : "=r"(a) : "l"(p));
    return a;
}
__device__ __forceinline__ float ex2f(float x) {
    float r;
    asm("ex2.approx.ftz.f32 %0, %1;" : "=f"(r) : "f"(x));
    return r;
}
#define CVT2(r, a, b) \
    asm("cvt.rn.satfinite.bf16x2.f32 %0, %1, %2;" : "=r"(r) : "f"(b), "f"(a))
#define CP_ASYNC16(dst, src) \
    asm volatile("cp.async.cg.shared.global [%0], [%1], 16;" :: "r"(dst), "l"(src) : "memory")
#define CP_COMMIT() asm volatile("cp.async.commit_group;" ::: "memory")
#define CP_WAIT0()  asm volatile("cp.async.wait_group 0;" ::: "memory")

#define LDSM_X2(r0, r1, a) \
    asm volatile("ldmatrix.sync.aligned.m8n8.x2.shared.b16 {%0,%1}, [%2];" \
                 : "=r"(r0), "=r"(r1) : "r"(a))
#define LDSM_X4(r0, r1, r2, r3, a) \
    asm volatile("ldmatrix.sync.aligned.m8n8.x4.shared.b16 {%0,%1,%2,%3}, [%4];" \
                 : "=r"(r0), "=r"(r1), "=r"(r2), "=r"(r3) : "r"(a))

__device__ __forceinline__ void mma_k8(float& c0, float& c1, float& c2, float& c3,
                                       uint32_t a0, uint32_t a1, uint32_t b0) {
    asm volatile(
        "mma.sync.aligned.m16n8k8.row.col.f32.bf16.bf16.f32 "
        "{%0,%1,%2,%3}, {%4,%5}, {%6}, {%0,%1,%2,%3};"
        : "+f"(c0), "+f"(c1), "+f"(c2), "+f"(c3)
        : "r"(a0), "r"(a1), "r"(b0));
}
__device__ __forceinline__ void mma_k16(float* c, const uint32_t* a,
                                        uint32_t b0, uint32_t b1) {
    asm volatile(
        "mma.sync.aligned.m16n8k16.row.col.f32.bf16.bf16.f32 "
        "{%0,%1,%2,%3}, {%4,%5,%6,%7}, {%8,%9}, {%0,%1,%2,%3};"
        : "+f"(c[0]), "+f"(c[1]), "+f"(c[2]), "+f"(c[3])
        : "r"(a[0]), "r"(a[1]), "r"(a[2]), "r"(a[3]), "r"(b0), "r"(b1));
}

// exp(s/8) = 2^(s * 0.125*log2e); scale folded into Q
#define QSCALE (0.125f * 1.4426950408889634f)

// ---------------------------------------------------------------------------
// Kernel 1: QKV projections + SE partial channel sums.
// 256 CTAs x 128 thr, 64 pixels/CTA; x staged via smem.
// ---------------------------------------------------------------------------
__global__ void __launch_bounds__(128) qkv_kernel(
    const float* __restrict__ x,
    const float* __restrict__ Wq, const float* __restrict__ bq,
    const float* __restrict__ Wk, const float* __restrict__ bk,
    const float* __restrict__ Wv, const float* __restrict__ bv) {
    __shared__ float sX[C * 64];                 // [c][px] 16KB
    __shared__ float sWq[8 * C], sWk[8 * C], sWv[C * C];
    __shared__ float sbq[8], sbk[8], sbv[C];
    __shared__ float spart[128];

    int t = threadIdx.x;
    for (int i = t; i < 8 * C; i += 128) { sWq[i] = Wq[i]; sWk[i] = Wk[i]; }
    for (int i = t; i < C * C; i += 128) sWv[i] = Wv[i];
    if (t < 8) { sbq[t] = bq[t]; sbk[t] = bk[t]; }
    if (t < C) sbv[t] = bv[t];

    int pix0 = blockIdx.x * 64;
    int bb = pix0 >> 12, n0 = pix0 & (N - 1);
    {
        const float4* xs = (const float4*)(x + (size_t)bb * C * N + n0);
        float4* xd = (float4*)sX;
#pragma unroll
        for (int j = 0; j < 8; j++) {
            int id = t + 128 * j;
            int row = id >> 4, col = id & 15;
            xd[row * 16 + col] = xs[(size_t)row * (N / 4) + col];
        }
    }
    __syncthreads();

    // SE partial: per-channel sums over this CTA's 64 pixels (skewed, bank-free)
    {
        int ch = t & 63, hp = t >> 6;
        float s = 0.0f;
#pragma unroll
        for (int i = 0; i < 32; i++)
            s += sX[ch * 64 + hp * 32 + ((t + i) & 31)];
        spart[t] = s;
    }

    int half = t >> 6, px = t & 63;
    int pix = pix0 + px, n = n0 + px;

    if (half == 0) {
        float qa[8], ka[8], va[24];
#pragma unroll
        for (int o = 0; o < 8; o++) { qa[o] = sbq[o]; ka[o] = sbk[o]; }
#pragma unroll
        for (int v = 0; v < 24; v++) va[v] = sbv[v];
#pragma unroll 4
        for (int c = 0; c < C; c++) {
            float xc = sX[c * 64 + px];
#pragma unroll
            for (int o = 0; o < 8; o++) {
                qa[o] = fmaf(sWq[o * C + c], xc, qa[o]);
                ka[o] = fmaf(sWk[o * C + c], xc, ka[o]);
            }
#pragma unroll
            for (int v = 0; v < 24; v++) va[v] = fmaf(sWv[v * C + c], xc, va[v]);
        }
        uint32_t w[4], u[4];
#pragma unroll
        for (int j = 0; j < 4; j++) {
            CVT2(w[j], qa[2 * j] * QSCALE, qa[2 * j + 1] * QSCALE);
            CVT2(u[j], ka[2 * j], ka[2 * j + 1]);
        }
        *(uint4*)(g_Qb + (size_t)pix * 8) = make_uint4(w[0], w[1], w[2], w[3]);
        *(uint4*)(g_Kb + (size_t)pix * 8) = make_uint4(u[0], u[1], u[2], u[3]);
#pragma unroll
        for (int v = 0; v < 24; v++)
            g_Vt[((size_t)bb * C + v) * N + n] = __float2bfloat16(va[v]);
    } else {
        float va[40];
#pragma unroll
        for (int v = 0; v < 40; v++) va[v] = sbv[24 + v];
#pragma unroll 4
        for (int c = 0; c < C; c++) {
            float xc = sX[c * 64 + px];
#pragma unroll
            for (int v = 0; v < 40; v++) va[v] = fmaf(sWv[(24 + v) * C + c], xc, va[v]);
        }
#pragma unroll
        for (int v = 0; v < 40; v++)
            g_Vt[((size_t)bb * C + 24 + v) * N + n] = __float2bfloat16(va[v]);
    }

    __syncthreads();
    if (t < C)
        g_part[((size_t)bb * 64 + (blockIdx.x & 63)) * C + t] = spart[t] + spart[t + 64];
}

// ---------------------------------------------------------------------------
// Kernel 2: SE gate MLP. 4 blocks x 64 thr; sums the per-CTA partials.
// ---------------------------------------------------------------------------
__global__ void gate_mlp_kernel(const float* __restrict__ W1, const float* __restrict__ b1,
                                const float* __restrict__ W2, const float* __restrict__ b2) {
    __shared__ float savg[C];
    __shared__ float shid[4];
    int b = blockIdx.x, t = threadIdx.x;   // 64 threads
    float s = 0.0f;
#pragma unroll 8
    for (int j = 0; j < 64; j++) s += g_part[((size_t)b * 64 + j) * C + t];
    savg[t] = s * (1.0f / (float)N);
    __syncthreads();
    if (t < 4) {
        float h = b1[t];
#pragma unroll
        for (int c = 0; c < C; c++) h = fmaf(W1[t * C + c], savg[c], h);
        shid[t] = fmaxf(h, 0.0f);
    }
    __syncthreads();
    float gg = b2[t];
#pragma unroll
    for (int j = 0; j < 4; j++) gg = fmaf(W2[t * 4 + j], shid[j], gg);
    g_gate[b * C + t] = 1.0f / (1.0f + __expf(-gg));
}

// ---------------------------------------------------------------------------
// Kernel 3: HMMA flash attention. 256 CTAs x 256 thr (8 warps).
// Warp w: qg = w&3 (16 queries), kh = w>>2 (2048-key half).
// All warps share the K/V smem tiles (both halves staged per iteration).
// smem: gate 256B | K [2kh][2buf][128x16B] | V [2kh][2buf][64x272B]
// ---------------------------------------------------------------------------
#define OFF_GATE 0
#define OFF_K    256
#define OFF_V    (256 + 8192)
#define SMEM_ATTN (256 + 8192 + 4 * 17408)
#define VPITCH 272
#define REDP 66

__global__ void __launch_bounds__(256, 2) attn_kernel(float* __restrict__ out) {
    extern __shared__ char dsm[];
    uint32_t sb = smem_u32(dsm);
    int tid = threadIdx.x, w = tid >> 5, lane = tid & 31;
    int g = lane >> 2, t4 = lane & 3;
    int qg = w & 3, kh = w >> 2;
    int bb = blockIdx.x >> 6, qb = blockIdx.x & 63;
    int q0 = qb * 64 + qg * 16;

    if (tid < C) ((float*)(dsm + OFF_GATE))[tid] = g_gate[bb * C + tid];

    // Q fragments: rows q0+g, q0+8+g
    uint32_t qa[2];
    {
        const __nv_bfloat16* Qp = g_Qb + ((size_t)bb * N + q0) * 8 + t4 * 2;
        qa[0] = *(const uint32_t*)(Qp + (size_t)g * 8);
        qa[1] = *(const uint32_t*)(Qp + (size_t)(8 + g) * 8);
    }

    const char* kgb = (const char*)(g_Kb + (size_t)bb * N * 8);
    const char* vgb = (const char*)(g_Vt + (size_t)bb * C * N);

    // staging: K one 16B/thread, V eight 16B/thread (2048 data chunks)
    int kkey = tid & 127, khh = tid >> 7;

    // fragment bases (warp-local key half)
    uint32_t kfb = sb + OFF_K + kh * 4096 + (lane & 15) * 16;
    int vg2 = lane >> 3, vr = lane & 7;
    uint32_t vfb = sb + OFF_V + kh * 34816
                 + (uint32_t)(((vg2 >> 1) * 8 + vr) * VPITCH + (vg2 & 1) * 16);

    // prologue: stage tile 0 of both halves into buf 0
    CP_ASYNC16(sb + OFF_K + khh * 4096 + kkey * 16,
               kgb + ((size_t)(khh * 2048) + kkey) * 16);
#pragma unroll
    for (int j = 0; j < 8; j++) {
        int id = tid + 256 * j, row = id >> 4, c16 = id & 15;
        int ch = row & 63, k2 = row >> 6;
        CP_ASYNC16(sb + OFF_V + k2 * 34816 + ch * VPITCH + c16 * 16,
                   vgb + ((size_t)ch * N + k2 * 2048) * 2 + c16 * 16);
    }
    CP_COMMIT();

    float o[8][4] = {};
    float sum0 = 0.0f, sum1 = 0.0f;

#pragma unroll 1
    for (int kt = 0; kt < 16; kt++) {
        int buf = kt & 1;
        CP_WAIT0();
        __syncthreads();
        if (kt + 1 < 16) {
            int nb = (kt + 1) & 1;
            int key0 = khh * 2048 + (kt + 1) * 128;
            CP_ASYNC16(sb + OFF_K + khh * 4096 + nb * 2048 + kkey * 16,
                       kgb + ((size_t)key0 + kkey) * 16);
#pragma unroll
            for (int j = 0; j < 8; j++) {
                int id = tid + 256 * j, row = id >> 4, c16 = id & 15;
                int ch = row & 63, k2 = row >> 6;
                CP_ASYNC16(sb + OFF_V + k2 * 34816 + nb * 17408 + ch * VPITCH + c16 * 16,
                           vgb + ((size_t)ch * N + k2 * 2048 + (kt + 1) * 128) * 2 + c16 * 16);
            }
            CP_COMMIT();
        }
        uint32_t ka = kfb + buf * 2048;
        uint32_t va = vfb + buf * 17408;
#pragma unroll
        for (int nt2 = 0; nt2 < 8; nt2++) {
            uint32_t kk0, kk1;
            LDSM_X2(kk0, kk1, ka + nt2 * 256);
            float c0 = 0, c1 = 0, c2 = 0, c3 = 0, c4 = 0, c5 = 0, c6 = 0, c7 = 0;
            mma_k8(c0, c1, c2, c3, qa[0], qa[1], kk0);
            mma_k8(c4, c5, c6, c7, qa[0], qa[1], kk1);
            float p0 = ex2f(c0), p1 = ex2f(c1), p2 = ex2f(c2), p3 = ex2f(c3);
            float p4 = ex2f(c4), p5 = ex2f(c5), p6 = ex2f(c6), p7 = ex2f(c7);
            sum0 += (p0 + p1) + (p4 + p5);      // row g
            sum1 += (p2 + p3) + (p6 + p7);      // row g+8
            uint32_t a[4];
            CVT2(a[0], p0, p1);
            CVT2(a[1], p2, p3);
            CVT2(a[2], p4, p5);
            CVT2(a[3], p6, p7);
#pragma unroll
            for (int cp = 0; cp < 4; cp++) {
                uint32_t b0, b1, b2, b3;
                LDSM_X4(b0, b1, b2, b3, va + cp * (16 * VPITCH) + nt2 * 32);
                mma_k16(o[2 * cp], a, b0, b1);
                mma_k16(o[2 * cp + 1], a, b2, b3);
            }
        }
    }

    sum0 += __shfl_xor_sync(0xFFFFFFFFu, sum0, 1);
    sum0 += __shfl_xor_sync(0xFFFFFFFFu, sum0, 2);
    sum1 += __shfl_xor_sync(0xFFFFFFFFu, sum1, 1);
    sum1 += __shfl_xor_sync(0xFFFFFFFFu, sum1, 2);

    __syncthreads();   // all warps done with V smem; overlay reduction buffers
    float* red  = (float*)(dsm + OFF_V) + qg * (16 * REDP);
    float* reds = (float*)(dsm + OFF_V) + 4 * (16 * REDP);   // [4][16]

    if (kh == 1) {
#pragma unroll
        for (int ct = 0; ct < 8; ct++)
#pragma unroll
            for (int i = 0; i < 4; i++) {
                int row = g + (i >> 1) * 8;
                red[row * REDP + ct * 8 + t4 * 2 + (i & 1)] = o[ct][i];
            }
        if (t4 == 0) { reds[qg * 16 + g] = sum0; reds[qg * 16 + 8 + g] = sum1; }
    }
    __syncthreads();
    if (kh == 0) {
        float inv0 = 1.0f / (sum0 + reds[qg * 16 + g]);
        float inv1 = 1.0f / (sum1 + reds[qg * 16 + 8 + g]);
        const float* gt = (const float*)(dsm + OFF_GATE);
        float* outb = out + (size_t)bb * C * N;
#pragma unroll
        for (int ct = 0; ct < 8; ct++)
#pragma unroll
            for (int i = 0; i < 4; i++) {
                int row = g + (i >> 1) * 8;
                int ch = ct * 8 + t4 * 2 + (i & 1);
                float v = o[ct][i] + red[row * REDP + ch];
                outb[(size_t)ch * N + q0 + row] = v * ((i >> 1) ? inv1 : inv0) * gt[ch];
            }
    }
}

// ---------------------------------------------------------------------------
extern "C" void kernel_launch(void* const* d_in, const int* in_sizes, int n_in,
                              void* d_out, int out_size) {
    const float* x  = (const float*)d_in[0];
    const float* Wq = (const float*)d_in[1];
    const float* bq = (const float*)d_in[2];
    const float* Wk = (const float*)d_in[3];
    const float* bk = (const float*)d_in[4];
    const float* Wv = (const float*)d_in[5];
    const float* bv = (const float*)d_in[6];
    const float* W1 = (const float*)d_in[7];
    const float* b1 = (const float*)d_in[8];
    const float* W2 = (const float*)d_in[9];
    const float* b2 = (const float*)d_in[10];
    float* out = (float*)d_out;

    static int smem_set = 0;
    if (!smem_set) {
        cudaFuncSetAttribute(attn_kernel, cudaFuncAttributeMaxDynamicSharedMemorySize, SMEM_ATTN);
        smem_set = 1;
    }

    qkv_kernel<<<256, 128>>>(x, Wq, bq, Wk, bk, Wv, bv);
    gate_mlp_kernel<<<B, C>>>(W1, b1, W2, b2);
    attn_kernel<<<B * 64, 256, SMEM_ATTN>>>(out);
}